// round 5
// baseline (speedup 1.0000x reference)
#include <cuda_runtime.h>
#include <cstdint>

#define H      128
#define NREL   237
#define NB     100
#define RTILE  16
#define MT     64
#define XPITCH 132
#define MAXN   15000
#define MAXE   400000
#define EM     128        // edges per tile
#define ESPLIT 4          // splits per relation for edge kernel
#define BP     132        // smem pitch (floats) for A and B tiles

// ---------------- device-global scratch (no runtime allocation) -------------
__device__ float g_W[NREL * H * H];      // per-relation W^T[n][k]  (15.5 MB)
__device__ float g_x0[MAXN * H];
__device__ float g_h1[MAXN * H];
__device__ float g_M[MAXE * H];          // edge messages, rel-sorted (204.8 MB)
__device__ int   g_perm[MAXE];           // rel-sorted pos -> edge id
__device__ int   g_rpos[MAXE];           // edge id -> rel-sorted pos
__device__ int   g_dlist[MAXE];          // dst-sorted pos -> message row (rpos)
__device__ int   g_counts[256];
__device__ int   g_start[256];
__device__ int   g_cursor[256];
__device__ int   g_dcount[MAXN];
__device__ int   g_dstart[MAXN + 1];
__device__ int   g_dcursor[MAXN];

static const int SMEM_NODE = (H * H + MT * XPITCH) * 4 + MT * 4;     // 99584
static const int SMEM_EDGE = (2 * 128 * BP) * 4;                     // 135168

// single dynamic-smem symbol for the whole TU
extern __shared__ char dyn_smem[];

// ---------------- PTX helpers ------------------------------------------------
__device__ __forceinline__ uint32_t cvt_tf32(float x) {
    uint32_t r;
    asm("cvt.rn.tf32.f32 %0, %1;" : "=r"(r) : "f"(x));
    return r;
}
__device__ __forceinline__ void mma_16n8k8(float* c, const uint32_t* a,
                                           uint32_t b0, uint32_t b1) {
    asm volatile(
        "mma.sync.aligned.m16n8k8.row.col.f32.tf32.tf32.f32 "
        "{%0,%1,%2,%3}, {%4,%5,%6,%7}, {%8,%9}, {%0,%1,%2,%3};"
        : "+f"(c[0]), "+f"(c[1]), "+f"(c[2]), "+f"(c[3])
        : "r"(a[0]), "r"(a[1]), "r"(a[2]), "r"(a[3]), "r"(b0), "r"(b1));
}
__device__ __forceinline__ uint32_t f2u(float x) { return __float_as_uint(x); }

// ---------------- prep kernels -----------------------------------------------
__global__ void gather_x0_kernel(const float* __restrict__ emb,
                                 const int* __restrict__ nids, int n) {
    int idx = blockIdx.x * blockDim.x + threadIdx.x;
    if (idx < n * 32) {
        int node = idx >> 5, c = idx & 31;
        ((float4*)g_x0)[idx] = ((const float4*)emb)[(size_t)nids[node] * 32 + c];
    }
}
__global__ void zero_counts_kernel() { g_counts[threadIdx.x] = 0; }

__global__ void hist_kernel(const int* __restrict__ etype, int E) {
    __shared__ int sh[256];
    sh[threadIdx.x] = 0;
    __syncthreads();
    for (int e = blockIdx.x * blockDim.x + threadIdx.x; e < E;
         e += gridDim.x * blockDim.x)
        atomicAdd(&sh[etype[e]], 1);
    __syncthreads();
    int v = sh[threadIdx.x];
    if (v) atomicAdd(&g_counts[threadIdx.x], v);
}
__global__ void scan_kernel() {
    __shared__ int s[256];
    int t = threadIdx.x;
    int c = g_counts[t];
    s[t] = c;
    __syncthreads();
    #pragma unroll
    for (int off = 1; off < 256; off <<= 1) {
        int v = (t >= off) ? s[t - off] : 0;
        __syncthreads();
        s[t] += v;
        __syncthreads();
    }
    g_start[t] = s[t] - c;
    g_cursor[t] = s[t] - c;
}
__global__ void scatter_kernel(const int* __restrict__ etype, int E) {
    for (int e = blockIdx.x * blockDim.x + threadIdx.x; e < E;
         e += gridDim.x * blockDim.x) {
        int p = atomicAdd(&g_cursor[etype[e]], 1);
        g_perm[p] = e;
        g_rpos[e] = p;
    }
}
__global__ void zero_dcount_kernel(int n) {
    int i = blockIdx.x * blockDim.x + threadIdx.x;
    if (i < n) g_dcount[i] = 0;
}
__global__ void dhist_kernel(const int* __restrict__ dst, int E) {
    for (int e = blockIdx.x * blockDim.x + threadIdx.x; e < E;
         e += gridDim.x * blockDim.x)
        atomicAdd(&g_dcount[dst[e]], 1);
}
// single-block scan over n node counters
__global__ void dscan_kernel(int n) {
    __shared__ int s[1024];
    __shared__ int carry;
    int t = threadIdx.x;
    if (t == 0) carry = 0;
    __syncthreads();
    for (int base = 0; base < n; base += 1024) {
        int i = base + t;
        int c = (i < n) ? g_dcount[i] : 0;
        s[t] = c;
        __syncthreads();
        #pragma unroll
        for (int off = 1; off < 1024; off <<= 1) {
            int v = (t >= off) ? s[t - off] : 0;
            __syncthreads();
            s[t] += v;
            __syncthreads();
        }
        if (i < n) {
            int ex = carry + s[t] - c;
            g_dstart[i] = ex;
            g_dcursor[i] = ex;
        }
        __syncthreads();
        if (t == 0) carry += s[1023];
        __syncthreads();
    }
    if (t == 0) g_dstart[n] = carry;
}
__global__ void dscatter_kernel(const int* __restrict__ dst, int E) {
    for (int e = blockIdx.x * blockDim.x + threadIdx.x; e < E;
         e += gridDim.x * blockDim.x) {
        int p = atomicAdd(&g_dcursor[dst[e]], 1);
        g_dlist[p] = g_rpos[e];
    }
}

// W^T[r][n][k] = sum_b comp[r,b] * V[b][k][n]
__global__ void wbuild_kernel(const float* __restrict__ V,
                              const float* __restrict__ comp) {
    __shared__ float sC[RTILE * NB];
    int r0 = blockIdx.y * RTILE;
    for (int i = threadIdx.x; i < RTILE * NB; i += 128) {
        int rr = i / NB, b = i % NB;
        int r = r0 + rr;
        sC[i] = (r < NREL) ? comp[r * NB + b] : 0.f;
    }
    __syncthreads();
    int j = blockIdx.x * 128 + threadIdx.x;
    float acc[RTILE];
    #pragma unroll
    for (int rr = 0; rr < RTILE; rr++) acc[rr] = 0.f;
    #pragma unroll 4
    for (int b = 0; b < NB; b++) {
        float v = V[(size_t)b * (H * H) + j];
        #pragma unroll
        for (int rr = 0; rr < RTILE; rr++) acc[rr] += sC[rr * NB + b] * v;
    }
    int k = j >> 7, n = j & 127;
    #pragma unroll
    for (int rr = 0; rr < RTILE; rr++) {
        int r = r0 + rr;
        if (r < NREL) g_W[(size_t)r * (H * H) + n * 128 + k] = acc[rr];
    }
}

// ---------------- dense self-loop GEMM: out = x @ W + bias (FFMA) -----------
__global__ void node_gemm_kernel(const float* __restrict__ xin,
                                 const float* __restrict__ wmat,
                                 const float* __restrict__ bias,
                                 float* __restrict__ out, int n) {
    float* smem = (float*)dyn_smem;
    float* sW = smem;
    float* sX = smem + H * H;
    {
        const float4* s4 = (const float4*)wmat;
        float4* d4 = (float4*)sW;
        for (int i = threadIdx.x; i < (H * H) / 4; i += 256) d4[i] = s4[i];
    }
    int m0 = blockIdx.x * MT;
    int tsize = min(MT, n - m0);
    int mrow = threadIdx.x >> 2, dg = threadIdx.x & 3;
    if (mrow < tsize) {
        const float4* xr = (const float4*)&xin[(size_t)(m0 + mrow) * H];
        #pragma unroll
        for (int i = 0; i < 8; i++)
            *(float4*)&sX[mrow * XPITCH + dg * 32 + 4 * i] = xr[dg * 8 + i];
    } else {
        float4 z = make_float4(0.f, 0.f, 0.f, 0.f);
        #pragma unroll
        for (int i = 0; i < 8; i++)
            *(float4*)&sX[mrow * XPITCH + dg * 32 + 4 * i] = z;
    }
    __syncthreads();
    int tn = threadIdx.x & 31, tm = threadIdx.x >> 5;
    float acc[8][4];
    #pragma unroll
    for (int r = 0; r < 8; r++)
        #pragma unroll
        for (int c = 0; c < 4; c++) acc[r][c] = 0.f;
    const float* sxb = &sX[tm * 8 * XPITCH];
    #pragma unroll 4
    for (int k = 0; k < H; k++) {
        float4 b = *(const float4*)&sW[k * H + tn * 4];
        #pragma unroll
        for (int r = 0; r < 8; r++) {
            float a = sxb[r * XPITCH + k];
            acc[r][0] += a * b.x; acc[r][1] += a * b.y;
            acc[r][2] += a * b.z; acc[r][3] += a * b.w;
        }
    }
    float4 bj = *(const float4*)&bias[tn * 4];
    #pragma unroll
    for (int r = 0; r < 8; r++) {
        int row = tm * 8 + r;
        if (row < tsize) {
            float4 o = make_float4(acc[r][0] + bj.x, acc[r][1] + bj.y,
                                   acc[r][2] + bj.z, acc[r][3] + bj.w);
            *(float4*)&out[(size_t)(m0 + row) * H + tn * 4] = o;
        }
    }
}

// ---------------- TF32 mma.sync edge GEMM -> message buffer -----------------
// CTA: 256 threads = 8 warps. Warp (wm, wn). Tile: 128 edges x 128 out, K=128.
// Messages written to g_M at their rel-sorted row (t0 + local row): no atomics.
__global__ void __launch_bounds__(256, 1)
edge_mma_kernel(const float* __restrict__ xin,
                const int* __restrict__ src,
                const int* __restrict__ perm,
                const float* __restrict__ norm) {
    float* sA = (float*)dyn_smem;            // [128][BP]  A = norm * x[src] (tf32 bits)
    float* sB = sA + 128 * BP;               // [128][BP]  B = W^T[n][k]    (tf32 bits)

    int tid = threadIdx.x, lane = tid & 31, wid = tid >> 5;
    int g = lane >> 2, tig = lane & 3;
    int wm = wid >> 1, wn = wid & 1;
    int m0 = wm * 32, n0 = wn * 64;

    int rel = blockIdx.x / ESPLIT;
    int sp  = blockIdx.x % ESPLIT;
    int cnt = g_counts[rel], st = g_start[rel];
    int lo = st + (cnt * sp) / ESPLIT;
    int hi = st + (cnt * (sp + 1)) / ESPLIT;
    if (lo >= hi) return;

    // stage B = W^T[rel] once, converted to tf32
    {
        const float4* wt4 = (const float4*)(g_W + (size_t)rel * (H * H));
        for (int i = tid; i < 4096; i += 256) {
            float4 v = wt4[i];
            int n = i >> 5, k = (i & 31) << 2;
            uint4 t = make_uint4(cvt_tf32(v.x), cvt_tf32(v.y),
                                 cvt_tf32(v.z), cvt_tf32(v.w));
            *(uint4*)&sB[n * BP + k] = t;
        }
    }

    int arow = tid >> 1, ahalf = tid & 1;    // staging: 2 threads per edge row

    for (int t0 = lo; t0 < hi; t0 += EM) {
        int tsize = min(EM, hi - t0);
        __syncthreads();   // prior compute done (and B ready on first iter)

        // ---- stage A tile (tf32 bits, normalized) ----
        if (arow < tsize) {
            int e = perm[t0 + arow];
            float nrm = norm[e];
            const float4* xr = (const float4*)(xin + (size_t)src[e] * H);
            #pragma unroll
            for (int i = 0; i < 16; i++) {
                float4 v = xr[ahalf * 16 + i];
                uint4 t = make_uint4(cvt_tf32(v.x * nrm), cvt_tf32(v.y * nrm),
                                     cvt_tf32(v.z * nrm), cvt_tf32(v.w * nrm));
                *(uint4*)&sA[arow * BP + ahalf * 64 + i * 4] = t;
            }
        } else {
            uint4 z = make_uint4(0, 0, 0, 0);
            #pragma unroll
            for (int i = 0; i < 16; i++)
                *(uint4*)&sA[arow * BP + ahalf * 64 + i * 4] = z;
        }
        __syncthreads();

        // ---- compute: warp tile 32x64, K=128 in 16 k-steps of 8 ----
        float acc[2][8][4];
        #pragma unroll
        for (int mi = 0; mi < 2; mi++)
            #pragma unroll
            for (int ni = 0; ni < 8; ni++)
                #pragma unroll
                for (int c = 0; c < 4; c++) acc[mi][ni][c] = 0.f;

        #pragma unroll 2
        for (int ks = 0; ks < 16; ks++) {
            int k0 = ks * 8;
            uint32_t a[2][4];
            #pragma unroll
            for (int mi = 0; mi < 2; mi++) {
                const float* ap = &sA[(m0 + mi * 16 + g) * BP + k0 + tig];
                a[mi][0] = f2u(ap[0]);
                a[mi][1] = f2u(ap[8 * BP]);
                a[mi][2] = f2u(ap[4]);
                a[mi][3] = f2u(ap[8 * BP + 4]);
            }
            #pragma unroll
            for (int ni = 0; ni < 8; ni++) {
                const float* bp = &sB[(n0 + ni * 8 + g) * BP + k0 + tig];
                uint32_t b0 = f2u(bp[0]);
                uint32_t b1 = f2u(bp[4]);
                mma_16n8k8(acc[0][ni], a[0], b0, b1);
                mma_16n8k8(acc[1][ni], a[1], b0, b1);
            }
        }

        // ---- store messages (plain STG, contiguous rows) ----
        #pragma unroll
        for (int mi = 0; mi < 2; mi++) {
            int r_lo = m0 + mi * 16 + g;
            int r_hi = r_lo + 8;
            bool v_lo = r_lo < tsize, v_hi = r_hi < tsize;
            float* plo = g_M + (size_t)(t0 + r_lo) * H;
            float* phi = g_M + (size_t)(t0 + r_hi) * H;
            #pragma unroll
            for (int ni = 0; ni < 8; ni++) {
                int c = n0 + ni * 8 + tig * 2;
                if (v_lo) *(float2*)(plo + c) =
                    make_float2(acc[mi][ni][0], acc[mi][ni][1]);
                if (v_hi) *(float2*)(phi + c) =
                    make_float2(acc[mi][ni][2], acc[mi][ni][3]);
            }
        }
    }
}

// ---------------- dst-sorted gather-reduce: out[v] += sum of messages -------
__global__ void gather_reduce_kernel(float* __restrict__ out, int n,
                                     int do_relu) {
    int v = blockIdx.x * 8 + (threadIdx.x >> 5);
    int lane = threadIdx.x & 31;
    if (v >= n) return;
    int q = g_dstart[v], qe = g_dstart[v + 1];
    const float4* M4 = (const float4*)g_M;
    float4 a0 = make_float4(0.f, 0.f, 0.f, 0.f);
    float4 a1 = make_float4(0.f, 0.f, 0.f, 0.f);
    for (; q + 2 <= qe; q += 2) {
        int r0 = g_dlist[q], r1 = g_dlist[q + 1];
        float4 m0 = M4[(size_t)r0 * 32 + lane];
        float4 m1 = M4[(size_t)r1 * 32 + lane];
        a0.x += m0.x; a0.y += m0.y; a0.z += m0.z; a0.w += m0.w;
        a1.x += m1.x; a1.y += m1.y; a1.z += m1.z; a1.w += m1.w;
    }
    if (q < qe) {
        int r0 = g_dlist[q];
        float4 m0 = M4[(size_t)r0 * 32 + lane];
        a0.x += m0.x; a0.y += m0.y; a0.z += m0.z; a0.w += m0.w;
    }
    float4* op = (float4*)out + (size_t)v * 32 + lane;
    float4 o = *op;
    o.x += a0.x + a1.x; o.y += a0.y + a1.y;
    o.z += a0.z + a1.z; o.w += a0.w + a1.w;
    if (do_relu) {
        o.x = fmaxf(o.x, 0.f); o.y = fmaxf(o.y, 0.f);
        o.z = fmaxf(o.z, 0.f); o.w = fmaxf(o.w, 0.f);
    }
    *op = o;
}

// ---------------- host orchestration ----------------------------------------
extern "C" void kernel_launch(void* const* d_in, const int* in_sizes, int n_in,
                              void* d_out, int out_size) {
    const int*   nids  = (const int*)d_in[0];
    const int*   src   = (const int*)d_in[1];
    const int*   dst   = (const int*)d_in[2];
    const int*   etype = (const int*)d_in[3];
    const float* norm  = (const float*)d_in[4];
    const float* emb   = (const float*)d_in[6];
    const float* V1    = (const float*)d_in[7];
    const float* comp1 = (const float*)d_in[8];
    const float* loop1 = (const float*)d_in[9];
    const float* bias1 = (const float*)d_in[10];
    const float* V2    = (const float*)d_in[11];
    const float* comp2 = (const float*)d_in[12];
    const float* loop2 = (const float*)d_in[13];
    const float* bias2 = (const float*)d_in[14];
    float* out = (float*)d_out;

    int nN = in_sizes[0];
    int E  = in_sizes[1];

    cudaFuncSetAttribute(node_gemm_kernel,
                         cudaFuncAttributeMaxDynamicSharedMemorySize, SMEM_NODE);
    cudaFuncSetAttribute(edge_mma_kernel,
                         cudaFuncAttributeMaxDynamicSharedMemorySize, SMEM_EDGE);

    float *px0 = nullptr, *ph1 = nullptr;
    int* pperm = nullptr;
    cudaGetSymbolAddress((void**)&px0, g_x0);
    cudaGetSymbolAddress((void**)&ph1, g_h1);
    cudaGetSymbolAddress((void**)&pperm, g_perm);

    // prep: gather input, sort edges by relation, sort message rows by dst
    gather_x0_kernel<<<(nN * 32 + 255) / 256, 256>>>(emb, nids, nN);
    zero_counts_kernel<<<1, 256>>>();
    hist_kernel<<<256, 256>>>(etype, E);
    scan_kernel<<<1, 256>>>();
    scatter_kernel<<<256, 256>>>(etype, E);
    zero_dcount_kernel<<<(nN + 255) / 256, 256>>>(nN);
    dhist_kernel<<<256, 256>>>(dst, E);
    dscan_kernel<<<1, 1024>>>(nN);
    dscatter_kernel<<<256, 256>>>(dst, E);

    dim3 wgrid(H * H / 128, (NREL + RTILE - 1) / RTILE);
    int ngrid = (nN + MT - 1) / MT;
    int egrid = NREL * ESPLIT;
    int ggrid = (nN + 7) / 8;

    // ---- layer 1 ----
    wbuild_kernel<<<wgrid, 128>>>(V1, comp1);
    node_gemm_kernel<<<ngrid, 256, SMEM_NODE>>>(px0, loop1, bias1, ph1, nN);
    edge_mma_kernel<<<egrid, 256, SMEM_EDGE>>>(px0, src, pperm, norm);
    gather_reduce_kernel<<<ggrid, 256>>>(ph1, nN, 1);

    // ---- layer 2 ----
    wbuild_kernel<<<wgrid, 128>>>(V2, comp2);
    node_gemm_kernel<<<ngrid, 256, SMEM_NODE>>>(ph1, loop2, bias2, out, nN);
    edge_mma_kernel<<<egrid, 256, SMEM_EDGE>>>(ph1, src, pperm, norm);
    gather_reduce_kernel<<<ggrid, 256>>>(out, nN, 0);
}

// round 7
// speedup vs baseline: 1.2212x; 1.2212x over previous
#include <cuda_runtime.h>
#include <cstdint>

#define H      128
#define NREL   237
#define NB     100
#define RTILE  16
#define MT     64
#define XPITCH 132
#define MAXN   15000
#define MAXE   400000
#define EM     128        // edges per tile
#define ESPLIT 4          // splits per relation for edge kernel
#define BP     132        // smem pitch (floats) for A and B tiles
#define SORTB  148        // persistent blocks for fused sort (<= SM count)

// ---------------- device-global scratch (no runtime allocation) -------------
__device__ float g_W[NREL * H * H];      // per-relation W^T[n][k]  (15.5 MB)
__device__ float g_x0[MAXN * H];
__device__ float g_h1[MAXN * H];
__device__ int   g_perm[MAXE];           // rel-sorted pos -> edge id
__device__ int   g_counts[256];
__device__ int   g_start[256];
__device__ int   g_cursor[256];
__device__ unsigned g_barcnt;            // grid-barrier state (self-resetting)
__device__ unsigned g_barflag;

static const int SMEM_NODE = (H * H + MT * XPITCH) * 4 + MT * 4;     // 99584
static const int SMEM_EDGE = (2 * 128 * BP) * 4 + 128 * 8;           // 136192

extern __shared__ char dyn_smem[];

// ---------------- PTX helpers ------------------------------------------------
__device__ __forceinline__ uint32_t cvt_tf32(float x) {
    uint32_t r;
    asm("cvt.rn.tf32.f32 %0, %1;" : "=r"(r) : "f"(x));
    return r;
}
__device__ __forceinline__ void red_add_v4(float* p, float a, float b,
                                           float c, float d) {
    asm volatile("red.global.add.v4.f32 [%0], {%1,%2,%3,%4};"
                 :: "l"(p), "f"(a), "f"(b), "f"(c), "f"(d) : "memory");
}
__device__ __forceinline__ void mma_16n8k8(float* c, const uint32_t* a,
                                           uint32_t b0, uint32_t b1) {
    asm volatile(
        "mma.sync.aligned.m16n8k8.row.col.f32.tf32.tf32.f32 "
        "{%0,%1,%2,%3}, {%4,%5,%6,%7}, {%8,%9}, {%0,%1,%2,%3};"
        : "+f"(c[0]), "+f"(c[1]), "+f"(c[2]), "+f"(c[3])
        : "r"(a[0]), "r"(a[1]), "r"(a[2]), "r"(a[3]), "r"(b0), "r"(b1));
}
__device__ __forceinline__ uint32_t f2u(float x) { return __float_as_uint(x); }

// grid-wide barrier (persistent kernel, grid <= resident capacity).
// Generation-based: state self-restores across graph replays.
__device__ __forceinline__ void gridbar(int nb) {
    __syncthreads();
    if (threadIdx.x == 0) {
        unsigned old = *(volatile unsigned*)&g_barflag;
        __threadfence();
        unsigned t = atomicAdd(&g_barcnt, 1);
        if (t == (unsigned)nb - 1) {
            g_barcnt = 0;
            __threadfence();
            atomicAdd(&g_barflag, 1);
        } else {
            while (*(volatile unsigned*)&g_barflag == old) {}
        }
        __threadfence();
    }
    __syncthreads();
}

// ---------------- fused relation counting-sort (one launch) ------------------
__global__ void __launch_bounds__(256, 1)
sort_kernel(const int* __restrict__ etype, int E) {
    __shared__ int sh[256];
    __shared__ int ss[256];
    int b = blockIdx.x, nb = gridDim.x, tid = threadIdx.x;

    if (b == 0) g_counts[tid] = 0;
    gridbar(nb);

    sh[tid] = 0;
    __syncthreads();
    for (int e = b * 256 + tid; e < E; e += nb * 256)
        atomicAdd(&sh[etype[e]], 1);
    __syncthreads();
    if (sh[tid]) atomicAdd(&g_counts[tid], sh[tid]);
    gridbar(nb);

    if (b == 0) {
        int c = g_counts[tid];
        ss[tid] = c;
        __syncthreads();
        #pragma unroll
        for (int off = 1; off < 256; off <<= 1) {
            int v = (tid >= off) ? ss[tid - off] : 0;
            __syncthreads();
            ss[tid] += v;
            __syncthreads();
        }
        g_start[tid] = ss[tid] - c;
        g_cursor[tid] = ss[tid] - c;
    }
    gridbar(nb);

    for (int e = b * 256 + tid; e < E; e += nb * 256) {
        int p = atomicAdd(&g_cursor[etype[e]], 1);
        g_perm[p] = e;
    }
}

// W^T[r][n][k] = sum_b comp[r,b] * V[b][k][n]
__global__ void wbuild_kernel(const float* __restrict__ V,
                              const float* __restrict__ comp) {
    __shared__ float sC[RTILE * NB];
    int r0 = blockIdx.y * RTILE;
    for (int i = threadIdx.x; i < RTILE * NB; i += 128) {
        int rr = i / NB, b = i % NB;
        int r = r0 + rr;
        sC[i] = (r < NREL) ? comp[r * NB + b] : 0.f;
    }
    __syncthreads();
    int j = blockIdx.x * 128 + threadIdx.x;
    float acc[RTILE];
    #pragma unroll
    for (int rr = 0; rr < RTILE; rr++) acc[rr] = 0.f;
    #pragma unroll 4
    for (int b = 0; b < NB; b++) {
        float v = V[(size_t)b * (H * H) + j];
        #pragma unroll
        for (int rr = 0; rr < RTILE; rr++) acc[rr] += sC[rr * NB + b] * v;
    }
    int k = j >> 7, n = j & 127;
    #pragma unroll
    for (int rr = 0; rr < RTILE; rr++) {
        int r = r0 + rr;
        if (r < NREL) g_W[(size_t)r * (H * H) + n * 128 + k] = acc[rr];
    }
}

__global__ void relu_kernel(int n) {
    for (int i = blockIdx.x * blockDim.x + threadIdx.x; i < n;
         i += gridDim.x * blockDim.x)
        g_h1[i] = fmaxf(g_h1[i], 0.f);
}

// -------- dense self-loop GEMM: out = x @ W + bias; optional emb gather -----
__global__ void node_gemm_kernel(const float* __restrict__ xin,
                                 const int* __restrict__ nids,   // NULL: direct
                                 float* __restrict__ xcopy,      // NULL: skip
                                 const float* __restrict__ wmat,
                                 const float* __restrict__ bias,
                                 float* __restrict__ out, int n) {
    float* smem = (float*)dyn_smem;
    float* sW = smem;
    float* sX = smem + H * H;
    {
        const float4* s4 = (const float4*)wmat;
        float4* d4 = (float4*)sW;
        for (int i = threadIdx.x; i < (H * H) / 4; i += 256) d4[i] = s4[i];
    }
    int m0 = blockIdx.x * MT;
    int tsize = min(MT, n - m0);
    int mrow = threadIdx.x >> 2, dg = threadIdx.x & 3;
    if (mrow < tsize) {
        int row = m0 + mrow;
        int srow = nids ? nids[row] : row;
        const float4* xr = (const float4*)&xin[(size_t)srow * H];
        #pragma unroll
        for (int i = 0; i < 8; i++) {
            float4 v = xr[dg * 8 + i];
            *(float4*)&sX[mrow * XPITCH + dg * 32 + 4 * i] = v;
            if (xcopy)
                *(float4*)&xcopy[(size_t)row * H + dg * 32 + 4 * i] = v;
        }
    } else {
        float4 z = make_float4(0.f, 0.f, 0.f, 0.f);
        #pragma unroll
        for (int i = 0; i < 8; i++)
            *(float4*)&sX[mrow * XPITCH + dg * 32 + 4 * i] = z;
    }
    __syncthreads();
    int tn = threadIdx.x & 31, tm = threadIdx.x >> 5;
    float acc[8][4];
    #pragma unroll
    for (int r = 0; r < 8; r++)
        #pragma unroll
        for (int c = 0; c < 4; c++) acc[r][c] = 0.f;
    const float* sxb = &sX[tm * 8 * XPITCH];
    #pragma unroll 4
    for (int k = 0; k < H; k++) {
        float4 b = *(const float4*)&sW[k * H + tn * 4];
        #pragma unroll
        for (int r = 0; r < 8; r++) {
            float a = sxb[r * XPITCH + k];
            acc[r][0] += a * b.x; acc[r][1] += a * b.y;
            acc[r][2] += a * b.z; acc[r][3] += a * b.w;
        }
    }
    float4 bj = *(const float4*)&bias[tn * 4];
    #pragma unroll
    for (int r = 0; r < 8; r++) {
        int row = tm * 8 + r;
        if (row < tsize) {
            float4 o = make_float4(acc[r][0] + bj.x, acc[r][1] + bj.y,
                                   acc[r][2] + bj.z, acc[r][3] + bj.w);
            *(float4*)&out[(size_t)(m0 + row) * H + tn * 4] = o;
        }
    }
}

// ---------------- TF32 mma.sync edge GEMM + fused RED.v4 scatter -------------
// CTA: 256 threads = 8 warps, warp tile 32(M) x 64(N), K=128.
// Paired-k smem layout (LDS.64 fragments), register-prefetched A gather,
// B rows n-permuted so each thread's output quad is contiguous (RED.v4).
// norm applied in fp32 at the epilogue.
__global__ void __launch_bounds__(256, 1)
edge_mma_kernel(const float* __restrict__ xin,
                const int* __restrict__ src,
                const int* __restrict__ dst,
                const int* __restrict__ perm,
                const float* __restrict__ norm,
                float* __restrict__ hout) {
    float* sA = (float*)dyn_smem;            // [128][BP] paired-k tf32 bits
    float* sB = sA + 128 * BP;               // [128][BP] paired-k + n-perm
    int*   sDst = (int*)(sB + 128 * BP);     // [128]
    float* sNrm = (float*)(sDst + 128);      // [128]

    int tid = threadIdx.x, lane = tid & 31, wid = tid >> 5;
    int g = lane >> 2, tig = lane & 3;
    int wm = wid >> 1, wn = wid & 1;
    int m0 = wm * 32, n0 = wn * 64;

    int rel = blockIdx.x / ESPLIT;
    int sp  = blockIdx.x % ESPLIT;
    int cnt = g_counts[rel], st = g_start[rel];
    int lo = st + (cnt * sp) / ESPLIT;
    int hi = st + (cnt * (sp + 1)) / ESPLIT;
    if (lo >= hi) return;

    // ---- stage B = W^T[rel]: n-permuted rows, paired-k columns, tf32 ----
    // 128 rows x 16 k-groups x 8 floats = full 128x128 tile
    {
        const float* wt = g_W + (size_t)rel * (H * H);
        for (int u = tid; u < 2048; u += 256) {
            int srow = u >> 4;          // stored (logical) row 0..127
            int kg = u & 15;            // 8-col k-group 0..15
            int half = srow >> 6;
            int rem = srow & 63;
            int ni = rem >> 3, tg = (rem >> 1) & 3, bb = rem & 1;
            int an = half * 64 + (ni >> 1) * 16 + tg * 4 + (ni & 1) * 2 + bb;
            const float4* wr = (const float4*)(wt + (size_t)an * H);
            float4 u0 = wr[kg * 2], u1 = wr[kg * 2 + 1];
            float* d = &sB[srow * BP + kg * 8];
            *(uint4*)&d[0] = make_uint4(cvt_tf32(u0.x), cvt_tf32(u1.x),
                                        cvt_tf32(u0.y), cvt_tf32(u1.y));
            *(uint4*)&d[4] = make_uint4(cvt_tf32(u0.z), cvt_tf32(u1.z),
                                        cvt_tf32(u0.w), cvt_tf32(u1.w));
        }
    }

    int arow = tid >> 1, ahalf = tid & 1;    // 2 staging threads per edge row
    float4 pf[16];
    float pnrm = 0.f;
    int pdst = 0, pvalid = 0;

    // initial prefetch for first tile
    {
        int t0 = lo;
        if (t0 + arow < hi) {
            int e = perm[t0 + arow];
            if (ahalf == 0) { pnrm = norm[e]; pdst = dst[e]; }
            const float4* xr = (const float4*)(xin + (size_t)src[e] * H);
            #pragma unroll
            for (int i = 0; i < 16; i++) pf[i] = xr[ahalf * 16 + i];
            pvalid = 1;
        } else pvalid = 0;
    }

    for (int t0 = lo; t0 < hi; t0 += EM) {
        int tsize = min(EM, hi - t0);
        __syncthreads();   // prev compute done reading sA (also orders sB once)

        // ---- STS: paired-k tf32 from prefetch registers ----
        if (pvalid) {
            #pragma unroll
            for (int j = 0; j < 8; j++) {
                float4 u0 = pf[2 * j], u1 = pf[2 * j + 1];
                float* d = &sA[arow * BP + ahalf * 64 + j * 8];
                *(uint4*)&d[0] = make_uint4(cvt_tf32(u0.x), cvt_tf32(u1.x),
                                            cvt_tf32(u0.y), cvt_tf32(u1.y));
                *(uint4*)&d[4] = make_uint4(cvt_tf32(u0.z), cvt_tf32(u1.z),
                                            cvt_tf32(u0.w), cvt_tf32(u1.w));
            }
        } else {
            uint4 z = make_uint4(0, 0, 0, 0);
            #pragma unroll
            for (int j = 0; j < 8; j++) {
                float* d = &sA[arow * BP + ahalf * 64 + j * 8];
                *(uint4*)&d[0] = z;
                *(uint4*)&d[4] = z;
            }
        }
        if (ahalf == 0) { sDst[arow] = pdst; sNrm[arow] = pnrm; }
        __syncthreads();

        // ---- prefetch next tile (overlaps with MMA below) ----
        {
            int tn0 = t0 + EM;
            if (tn0 < hi) {
                if (tn0 + arow < hi) {
                    int e = perm[tn0 + arow];
                    if (ahalf == 0) { pnrm = norm[e]; pdst = dst[e]; }
                    const float4* xr =
                        (const float4*)(xin + (size_t)src[e] * H);
                    #pragma unroll
                    for (int i = 0; i < 16; i++) pf[i] = xr[ahalf * 16 + i];
                    pvalid = 1;
                } else pvalid = 0;
            }
        }

        // ---- compute: 16 ksteps of m16n8k8, LDS.64 fragments ----
        float acc[2][8][4];
        #pragma unroll
        for (int mi = 0; mi < 2; mi++)
            #pragma unroll
            for (int ni = 0; ni < 8; ni++)
                #pragma unroll
                for (int c = 0; c < 4; c++) acc[mi][ni][c] = 0.f;

        #pragma unroll 2
        for (int ks = 0; ks < 16; ks++) {
            int base = ks * 8 + 2 * tig;
            uint32_t a[2][4];
            #pragma unroll
            for (int mi = 0; mi < 2; mi++) {
                float2 alo = *(const float2*)&sA[(m0 + mi * 16 + g) * BP + base];
                float2 ahi = *(const float2*)&sA[(m0 + mi * 16 + g + 8) * BP + base];
                a[mi][0] = f2u(alo.x); a[mi][1] = f2u(ahi.x);
                a[mi][2] = f2u(alo.y); a[mi][3] = f2u(ahi.y);
            }
            #pragma unroll
            for (int ni = 0; ni < 8; ni++) {
                float2 bb = *(const float2*)&sB[(n0 + ni * 8 + g) * BP + base];
                uint32_t b0 = f2u(bb.x), b1 = f2u(bb.y);
                mma_16n8k8(acc[0][ni], a[0], b0, b1);
                mma_16n8k8(acc[1][ni], a[1], b0, b1);
            }
        }

        // ---- epilogue: scale by norm (fp32) and RED.v4 scatter ----
        #pragma unroll
        for (int mi = 0; mi < 2; mi++) {
            int r0 = m0 + mi * 16 + g;
            int r1 = r0 + 8;
            bool v0 = r0 < tsize, v1 = r1 < tsize;
            float nr0 = sNrm[r0], nr1 = sNrm[r1];
            float* p0 = hout + (size_t)sDst[r0] * H;
            float* p1 = hout + (size_t)sDst[r1] * H;
            #pragma unroll
            for (int q = 0; q < 4; q++) {
                int c = n0 + q * 16 + tig * 4;
                if (v0) red_add_v4(p0 + c,
                                   acc[mi][2 * q][0] * nr0,
                                   acc[mi][2 * q][1] * nr0,
                                   acc[mi][2 * q + 1][0] * nr0,
                                   acc[mi][2 * q + 1][1] * nr0);
                if (v1) red_add_v4(p1 + c,
                                   acc[mi][2 * q][2] * nr1,
                                   acc[mi][2 * q][3] * nr1,
                                   acc[mi][2 * q + 1][2] * nr1,
                                   acc[mi][2 * q + 1][3] * nr1);
            }
        }
    }
}

// ---------------- host orchestration ----------------------------------------
extern "C" void kernel_launch(void* const* d_in, const int* in_sizes, int n_in,
                              void* d_out, int out_size) {
    const int*   nids  = (const int*)d_in[0];
    const int*   src   = (const int*)d_in[1];
    const int*   dst   = (const int*)d_in[2];
    const int*   etype = (const int*)d_in[3];
    const float* norm  = (const float*)d_in[4];
    const float* emb   = (const float*)d_in[6];
    const float* V1    = (const float*)d_in[7];
    const float* comp1 = (const float*)d_in[8];
    const float* loop1 = (const float*)d_in[9];
    const float* bias1 = (const float*)d_in[10];
    const float* V2    = (const float*)d_in[11];
    const float* comp2 = (const float*)d_in[12];
    const float* loop2 = (const float*)d_in[13];
    const float* bias2 = (const float*)d_in[14];
    float* out = (float*)d_out;

    int nN = in_sizes[0];
    int E  = in_sizes[1];

    cudaFuncSetAttribute(node_gemm_kernel,
                         cudaFuncAttributeMaxDynamicSharedMemorySize, SMEM_NODE);
    cudaFuncSetAttribute(edge_mma_kernel,
                         cudaFuncAttributeMaxDynamicSharedMemorySize, SMEM_EDGE);

    float *px0 = nullptr, *ph1 = nullptr;
    int* pperm = nullptr;
    cudaGetSymbolAddress((void**)&px0, g_x0);
    cudaGetSymbolAddress((void**)&ph1, g_h1);
    cudaGetSymbolAddress((void**)&pperm, g_perm);

    dim3 wgrid(H * H / 128, (NREL + RTILE - 1) / RTILE);
    int ngrid = (nN + MT - 1) / MT;
    int egrid = NREL * ESPLIT;

    // launch order chosen so edge_mma_kernel is my 4th launch (ncu window)
    sort_kernel<<<SORTB, 256>>>(etype, E);                               // 0
    wbuild_kernel<<<wgrid, 128>>>(V1, comp1);                            // 1
    node_gemm_kernel<<<ngrid, 256, SMEM_NODE>>>(emb, nids, px0,
                                                loop1, bias1, ph1, nN);  // 2
    edge_mma_kernel<<<egrid, 256, SMEM_EDGE>>>(px0, src, dst, pperm,
                                               norm, ph1);               // 3
    relu_kernel<<<256, 256>>>(nN * H);                                   // 4
    wbuild_kernel<<<wgrid, 128>>>(V2, comp2);                            // 5
    node_gemm_kernel<<<ngrid, 256, SMEM_NODE>>>(ph1, nullptr, nullptr,
                                                loop2, bias2, out, nN);  // 6
    edge_mma_kernel<<<egrid, 256, SMEM_EDGE>>>(ph1, src, dst, pperm,
                                               norm, out);               // 7
}

// round 8
// speedup vs baseline: 1.2218x; 1.0005x over previous
#include <cuda_runtime.h>
#include <cstdint>

#define H      128
#define NREL   237
#define NB     100
#define RTILE  16
#define MT     64
#define XPITCH 132
#define MAXN   15000
#define MAXE   400000
#define EM     64         // edges per tile
#define ESPLIT 4          // splits per relation for edge kernel
#define BP     132        // smem pitch (floats) for A and B tiles
#define SORTB  148        // persistent blocks for fused sort (<= SM count)

// ---------------- device-global scratch (no runtime allocation) -------------
__device__ float g_W[NREL * H * H];      // per-relation W^T[n][k]  (15.5 MB)
__device__ float g_x0[MAXN * H];
__device__ float g_h1[MAXN * H];
__device__ int   g_perm[MAXE];           // rel-sorted pos -> edge id
__device__ int   g_counts[256];
__device__ int   g_start[256];
__device__ int   g_cursor[256];
__device__ unsigned g_barcnt;            // grid-barrier state (self-resetting)
__device__ unsigned g_barflag;

static const int SMEM_NODE = (H * H + MT * XPITCH) * 4 + MT * 4;     // 99584
static const int SMEM_EDGE = ((EM + 128) * BP) * 4 + EM * 8;         // 101888

extern __shared__ char dyn_smem[];

// ---------------- PTX helpers ------------------------------------------------
__device__ __forceinline__ uint32_t cvt_tf32(float x) {
    uint32_t r;
    asm("cvt.rn.tf32.f32 %0, %1;" : "=r"(r) : "f"(x));
    return r;
}
__device__ __forceinline__ void red_add_v4(float* p, float a, float b,
                                           float c, float d) {
    asm volatile("red.global.add.v4.f32 [%0], {%1,%2,%3,%4};"
                 :: "l"(p), "f"(a), "f"(b), "f"(c), "f"(d) : "memory");
}
__device__ __forceinline__ void mma_16n8k8(float* c, const uint32_t* a,
                                           uint32_t b0, uint32_t b1) {
    asm volatile(
        "mma.sync.aligned.m16n8k8.row.col.f32.tf32.tf32.f32 "
        "{%0,%1,%2,%3}, {%4,%5,%6,%7}, {%8,%9}, {%0,%1,%2,%3};"
        : "+f"(c[0]), "+f"(c[1]), "+f"(c[2]), "+f"(c[3])
        : "r"(a[0]), "r"(a[1]), "r"(a[2]), "r"(a[3]), "r"(b0), "r"(b1));
}
__device__ __forceinline__ uint32_t f2u(float x) { return __float_as_uint(x); }

// grid-wide barrier (persistent kernel, grid <= resident capacity).
__device__ __forceinline__ void gridbar(int nb) {
    __syncthreads();
    if (threadIdx.x == 0) {
        unsigned old = *(volatile unsigned*)&g_barflag;
        __threadfence();
        unsigned t = atomicAdd(&g_barcnt, 1);
        if (t == (unsigned)nb - 1) {
            g_barcnt = 0;
            __threadfence();
            atomicAdd(&g_barflag, 1);
        } else {
            while (*(volatile unsigned*)&g_barflag == old) {}
        }
        __threadfence();
    }
    __syncthreads();
}

// ---------------- fused relation counting-sort (one launch) ------------------
__global__ void __launch_bounds__(256, 1)
sort_kernel(const int* __restrict__ etype, int E) {
    __shared__ int sh[256];
    __shared__ int ss[256];
    int b = blockIdx.x, nb = gridDim.x, tid = threadIdx.x;

    if (b == 0) g_counts[tid] = 0;
    gridbar(nb);

    sh[tid] = 0;
    __syncthreads();
    for (int e = b * 256 + tid; e < E; e += nb * 256)
        atomicAdd(&sh[etype[e]], 1);
    __syncthreads();
    if (sh[tid]) atomicAdd(&g_counts[tid], sh[tid]);
    gridbar(nb);

    if (b == 0) {
        int c = g_counts[tid];
        ss[tid] = c;
        __syncthreads();
        #pragma unroll
        for (int off = 1; off < 256; off <<= 1) {
            int v = (tid >= off) ? ss[tid - off] : 0;
            __syncthreads();
            ss[tid] += v;
            __syncthreads();
        }
        g_start[tid] = ss[tid] - c;
        g_cursor[tid] = ss[tid] - c;
    }
    gridbar(nb);

    for (int e = b * 256 + tid; e < E; e += nb * 256) {
        int p = atomicAdd(&g_cursor[etype[e]], 1);
        g_perm[p] = e;
    }
}

// W^T[r][n][k] = sum_b comp[r,b] * V[b][k][n]
__global__ void wbuild_kernel(const float* __restrict__ V,
                              const float* __restrict__ comp) {
    __shared__ float sC[RTILE * NB];
    int r0 = blockIdx.y * RTILE;
    for (int i = threadIdx.x; i < RTILE * NB; i += 128) {
        int rr = i / NB, b = i % NB;
        int r = r0 + rr;
        sC[i] = (r < NREL) ? comp[r * NB + b] : 0.f;
    }
    __syncthreads();
    int j = blockIdx.x * 128 + threadIdx.x;
    float acc[RTILE];
    #pragma unroll
    for (int rr = 0; rr < RTILE; rr++) acc[rr] = 0.f;
    #pragma unroll 4
    for (int b = 0; b < NB; b++) {
        float v = V[(size_t)b * (H * H) + j];
        #pragma unroll
        for (int rr = 0; rr < RTILE; rr++) acc[rr] += sC[rr * NB + b] * v;
    }
    int k = j >> 7, n = j & 127;
    #pragma unroll
    for (int rr = 0; rr < RTILE; rr++) {
        int r = r0 + rr;
        if (r < NREL) g_W[(size_t)r * (H * H) + n * 128 + k] = acc[rr];
    }
}

__global__ void relu_kernel(int n) {
    for (int i = blockIdx.x * blockDim.x + threadIdx.x; i < n;
         i += gridDim.x * blockDim.x)
        g_h1[i] = fmaxf(g_h1[i], 0.f);
}

// -------- dense self-loop GEMM: out = x @ W + bias; optional emb gather -----
__global__ void node_gemm_kernel(const float* __restrict__ xin,
                                 const int* __restrict__ nids,   // NULL: direct
                                 float* __restrict__ xcopy,      // NULL: skip
                                 const float* __restrict__ wmat,
                                 const float* __restrict__ bias,
                                 float* __restrict__ out, int n) {
    float* smem = (float*)dyn_smem;
    float* sW = smem;
    float* sX = smem + H * H;
    {
        const float4* s4 = (const float4*)wmat;
        float4* d4 = (float4*)sW;
        for (int i = threadIdx.x; i < (H * H) / 4; i += 256) d4[i] = s4[i];
    }
    int m0 = blockIdx.x * MT;
    int tsize = min(MT, n - m0);
    int mrow = threadIdx.x >> 2, dg = threadIdx.x & 3;
    if (mrow < tsize) {
        int row = m0 + mrow;
        int srow = nids ? nids[row] : row;
        const float4* xr = (const float4*)&xin[(size_t)srow * H];
        #pragma unroll
        for (int i = 0; i < 8; i++) {
            float4 v = xr[dg * 8 + i];
            *(float4*)&sX[mrow * XPITCH + dg * 32 + 4 * i] = v;
            if (xcopy)
                *(float4*)&xcopy[(size_t)row * H + dg * 32 + 4 * i] = v;
        }
    } else {
        float4 z = make_float4(0.f, 0.f, 0.f, 0.f);
        #pragma unroll
        for (int i = 0; i < 8; i++)
            *(float4*)&sX[mrow * XPITCH + dg * 32 + 4 * i] = z;
    }
    __syncthreads();
    int tn = threadIdx.x & 31, tm = threadIdx.x >> 5;
    float acc[8][4];
    #pragma unroll
    for (int r = 0; r < 8; r++)
        #pragma unroll
        for (int c = 0; c < 4; c++) acc[r][c] = 0.f;
    const float* sxb = &sX[tm * 8 * XPITCH];
    #pragma unroll 4
    for (int k = 0; k < H; k++) {
        float4 b = *(const float4*)&sW[k * H + tn * 4];
        #pragma unroll
        for (int r = 0; r < 8; r++) {
            float a = sxb[r * XPITCH + k];
            acc[r][0] += a * b.x; acc[r][1] += a * b.y;
            acc[r][2] += a * b.z; acc[r][3] += a * b.w;
        }
    }
    float4 bj = *(const float4*)&bias[tn * 4];
    #pragma unroll
    for (int r = 0; r < 8; r++) {
        int row = tm * 8 + r;
        if (row < tsize) {
            float4 o = make_float4(acc[r][0] + bj.x, acc[r][1] + bj.y,
                                   acc[r][2] + bj.z, acc[r][3] + bj.w);
            *(float4*)&out[(size_t)(m0 + row) * H + tn * 4] = o;
        }
    }
}

// ---------------- TF32 mma.sync edge GEMM + fused RED.v4 scatter -------------
// CTA: 256 threads = 8 warps, warp tile 32(M) x 32(N), tile 64 edges x 128.
// EM=64 shrinks smem to ~100KB -> 2 CTAs/SM (occupancy 25%).
// Paired-k smem (LDS.64 fragments), register-prefetched A gather,
// B rows n-permuted so each thread's output quad is contiguous (RED.v4).
__global__ void __launch_bounds__(256, 2)
edge_mma_kernel(const float* __restrict__ xin,
                const int* __restrict__ src,
                const int* __restrict__ dst,
                const int* __restrict__ perm,
                const float* __restrict__ norm,
                float* __restrict__ hout) {
    float* sA = (float*)dyn_smem;            // [EM][BP] paired-k tf32 bits
    float* sB = sA + EM * BP;                // [128][BP] paired-k + n-perm
    int*   sDst = (int*)(sB + 128 * BP);     // [EM]
    float* sNrm = (float*)(sDst + EM);       // [EM]

    int tid = threadIdx.x, lane = tid & 31, wid = tid >> 5;
    int g = lane >> 2, tig = lane & 3;
    int wm = wid >> 2, wn = wid & 3;         // 2 x 4 warp grid
    int m0 = wm * 32, n0 = wn * 32;

    int rel = blockIdx.x / ESPLIT;
    int sp  = blockIdx.x % ESPLIT;
    int cnt = g_counts[rel], st = g_start[rel];
    int lo = st + (cnt * sp) / ESPLIT;
    int hi = st + (cnt * (sp + 1)) / ESPLIT;
    if (lo >= hi) return;

    // ---- stage B = W^T[rel]: n-permuted rows, paired-k columns, tf32 ----
    // 128 rows x 16 k-groups x 8 floats = full 128x128 tile
    {
        const float* wt = g_W + (size_t)rel * (H * H);
        for (int u = tid; u < 2048; u += 256) {
            int srow = u >> 4;          // stored (logical) row 0..127
            int kg = u & 15;            // 8-col k-group 0..15
            int half = srow >> 6;
            int rem = srow & 63;
            int ni = rem >> 3, tg = (rem >> 1) & 3, bb = rem & 1;
            int an = half * 64 + (ni >> 1) * 16 + tg * 4 + (ni & 1) * 2 + bb;
            const float4* wr = (const float4*)(wt + (size_t)an * H);
            float4 u0 = wr[kg * 2], u1 = wr[kg * 2 + 1];
            float* d = &sB[srow * BP + kg * 8];
            *(uint4*)&d[0] = make_uint4(cvt_tf32(u0.x), cvt_tf32(u1.x),
                                        cvt_tf32(u0.y), cvt_tf32(u1.y));
            *(uint4*)&d[4] = make_uint4(cvt_tf32(u0.z), cvt_tf32(u1.z),
                                        cvt_tf32(u0.w), cvt_tf32(u1.w));
        }
    }

    int arow = tid >> 2, aq = tid & 3;       // 4 staging threads per edge row
    float4 pf[8];
    float pnrm = 0.f;
    int pdst = 0, pvalid = 0;

    // initial prefetch for first tile
    {
        int t0 = lo;
        if (t0 + arow < hi) {
            int e = perm[t0 + arow];
            if (aq == 0) { pnrm = norm[e]; pdst = dst[e]; }
            const float4* xr = (const float4*)(xin + (size_t)src[e] * H);
            #pragma unroll
            for (int i = 0; i < 8; i++) pf[i] = xr[aq * 8 + i];
            pvalid = 1;
        } else pvalid = 0;
    }

    for (int t0 = lo; t0 < hi; t0 += EM) {
        int tsize = min(EM, hi - t0);
        __syncthreads();   // prev compute done reading sA (also orders sB once)

        // ---- STS: paired-k tf32 from prefetch registers ----
        if (pvalid) {
            #pragma unroll
            for (int j = 0; j < 4; j++) {
                float4 u0 = pf[2 * j], u1 = pf[2 * j + 1];
                float* d = &sA[arow * BP + aq * 32 + j * 8];
                *(uint4*)&d[0] = make_uint4(cvt_tf32(u0.x), cvt_tf32(u1.x),
                                            cvt_tf32(u0.y), cvt_tf32(u1.y));
                *(uint4*)&d[4] = make_uint4(cvt_tf32(u0.z), cvt_tf32(u1.z),
                                            cvt_tf32(u0.w), cvt_tf32(u1.w));
            }
        } else {
            uint4 z = make_uint4(0, 0, 0, 0);
            #pragma unroll
            for (int j = 0; j < 4; j++) {
                float* d = &sA[arow * BP + aq * 32 + j * 8];
                *(uint4*)&d[0] = z;
                *(uint4*)&d[4] = z;
            }
        }
        if (aq == 0) { sDst[arow] = pdst; sNrm[arow] = pnrm; }
        __syncthreads();

        // ---- prefetch next tile (overlaps with MMA below) ----
        {
            int tn0 = t0 + EM;
            if (tn0 < hi) {
                if (tn0 + arow < hi) {
                    int e = perm[tn0 + arow];
                    if (aq == 0) { pnrm = norm[e]; pdst = dst[e]; }
                    const float4* xr =
                        (const float4*)(xin + (size_t)src[e] * H);
                    #pragma unroll
                    for (int i = 0; i < 8; i++) pf[i] = xr[aq * 8 + i];
                    pvalid = 1;
                } else pvalid = 0;
            }
        }

        // ---- compute: 16 ksteps of m16n8k8, LDS.64 fragments ----
        float acc[2][4][4];
        #pragma unroll
        for (int mi = 0; mi < 2; mi++)
            #pragma unroll
            for (int ni = 0; ni < 4; ni++)
                #pragma unroll
                for (int c = 0; c < 4; c++) acc[mi][ni][c] = 0.f;

        #pragma unroll 4
        for (int ks = 0; ks < 16; ks++) {
            int base = ks * 8 + 2 * tig;
            uint32_t a[2][4];
            #pragma unroll
            for (int mi = 0; mi < 2; mi++) {
                float2 alo = *(const float2*)&sA[(m0 + mi * 16 + g) * BP + base];
                float2 ahi = *(const float2*)&sA[(m0 + mi * 16 + g + 8) * BP + base];
                a[mi][0] = f2u(alo.x); a[mi][1] = f2u(ahi.x);
                a[mi][2] = f2u(alo.y); a[mi][3] = f2u(ahi.y);
            }
            #pragma unroll
            for (int ni = 0; ni < 4; ni++) {
                float2 bb = *(const float2*)&sB[(n0 + ni * 8 + g) * BP + base];
                uint32_t b0 = f2u(bb.x), b1 = f2u(bb.y);
                mma_16n8k8(acc[0][ni], a[0], b0, b1);
                mma_16n8k8(acc[1][ni], a[1], b0, b1);
            }
        }

        // ---- epilogue: scale by norm (fp32) and RED.v4 scatter ----
        #pragma unroll
        for (int mi = 0; mi < 2; mi++) {
            int r0 = m0 + mi * 16 + g;
            int r1 = r0 + 8;
            bool v0 = r0 < tsize, v1 = r1 < tsize;
            float nr0 = sNrm[r0], nr1 = sNrm[r1];
            float* p0 = hout + (size_t)sDst[r0] * H;
            float* p1 = hout + (size_t)sDst[r1] * H;
            #pragma unroll
            for (int q = 0; q < 2; q++) {
                int c = n0 + q * 16 + tig * 4;
                if (v0) red_add_v4(p0 + c,
                                   acc[mi][2 * q][0] * nr0,
                                   acc[mi][2 * q][1] * nr0,
                                   acc[mi][2 * q + 1][0] * nr0,
                                   acc[mi][2 * q + 1][1] * nr0);
                if (v1) red_add_v4(p1 + c,
                                   acc[mi][2 * q][2] * nr1,
                                   acc[mi][2 * q][3] * nr1,
                                   acc[mi][2 * q + 1][2] * nr1,
                                   acc[mi][2 * q + 1][3] * nr1);
            }
        }
    }
}

// ---------------- host orchestration ----------------------------------------
extern "C" void kernel_launch(void* const* d_in, const int* in_sizes, int n_in,
                              void* d_out, int out_size) {
    const int*   nids  = (const int*)d_in[0];
    const int*   src   = (const int*)d_in[1];
    const int*   dst   = (const int*)d_in[2];
    const int*   etype = (const int*)d_in[3];
    const float* norm  = (const float*)d_in[4];
    const float* emb   = (const float*)d_in[6];
    const float* V1    = (const float*)d_in[7];
    const float* comp1 = (const float*)d_in[8];
    const float* loop1 = (const float*)d_in[9];
    const float* bias1 = (const float*)d_in[10];
    const float* V2    = (const float*)d_in[11];
    const float* comp2 = (const float*)d_in[12];
    const float* loop2 = (const float*)d_in[13];
    const float* bias2 = (const float*)d_in[14];
    float* out = (float*)d_out;

    int nN = in_sizes[0];
    int E  = in_sizes[1];

    cudaFuncSetAttribute(node_gemm_kernel,
                         cudaFuncAttributeMaxDynamicSharedMemorySize, SMEM_NODE);
    cudaFuncSetAttribute(edge_mma_kernel,
                         cudaFuncAttributeMaxDynamicSharedMemorySize, SMEM_EDGE);

    float *px0 = nullptr, *ph1 = nullptr;
    int* pperm = nullptr;
    cudaGetSymbolAddress((void**)&px0, g_x0);
    cudaGetSymbolAddress((void**)&ph1, g_h1);
    cudaGetSymbolAddress((void**)&pperm, g_perm);

    dim3 wgrid(H * H / 128, (NREL + RTILE - 1) / RTILE);
    int ngrid = (nN + MT - 1) / MT;
    int egrid = NREL * ESPLIT;

    // launch order chosen so edge_mma_kernel is my 4th launch (ncu window)
    sort_kernel<<<SORTB, 256>>>(etype, E);                               // 0
    wbuild_kernel<<<wgrid, 128>>>(V1, comp1);                            // 1
    node_gemm_kernel<<<ngrid, 256, SMEM_NODE>>>(emb, nids, px0,
                                                loop1, bias1, ph1, nN);  // 2
    edge_mma_kernel<<<egrid, 256, SMEM_EDGE>>>(px0, src, dst, pperm,
                                               norm, ph1);               // 3
    relu_kernel<<<256, 256>>>(nN * H);                                   // 4
    wbuild_kernel<<<wgrid, 128>>>(V2, comp2);                            // 5
    node_gemm_kernel<<<ngrid, 256, SMEM_NODE>>>(ph1, nullptr, nullptr,
                                                loop2, bias2, out, nN);  // 6
    edge_mma_kernel<<<egrid, 256, SMEM_EDGE>>>(ph1, src, dst, pperm,
                                               norm, out);               // 7
}

// round 9
// speedup vs baseline: 1.5636x; 1.2798x over previous
#include <cuda_runtime.h>
#include <cuda_fp16.h>
#include <cstdint>

#define H      128
#define NREL   237
#define NB     100
#define RTILE  16
#define MT     64
#define XPITCH 132
#define MAXN   15000
#define MAXE   400000
#define EM     128        // edges per tile
#define ESPLIT 2          // splits per relation for edge kernel
#define BPH    72         // smem pitch in uint32 (half2) units; 72%32==8 -> phase-conflict-free LDS.64
#define SORTB  148        // persistent blocks for fused sort (<= SM count)

// ---------------- device-global scratch (no runtime allocation) -------------
__device__ float g_W[NREL * H * H];      // per-relation W^T[n][k]  (15.5 MB)
__device__ float g_x0[MAXN * H];
__device__ float g_h1[MAXN * H];
__device__ int   g_perm[MAXE];           // rel-sorted pos -> edge id
__device__ int   g_counts[256];
__device__ int   g_start[256];
__device__ int   g_cursor[256];
__device__ unsigned g_barcnt;            // grid-barrier state (self-resetting)
__device__ unsigned g_barflag;

static const int SMEM_NODE = (H * H + MT * XPITCH) * 4 + MT * 4;     // 99584
static const int SMEM_EDGE = (2 * 128 * BPH) * 4 + EM * 8;           // 74752

extern __shared__ char dyn_smem[];

// ---------------- PTX helpers ------------------------------------------------
__device__ __forceinline__ uint32_t h2pack(float a, float b) {
    __half2 h = __floats2half2_rn(a, b);   // a -> low, b -> high
    return *(uint32_t*)&h;
}
__device__ __forceinline__ void red_add_v4(float* p, float a, float b,
                                           float c, float d) {
    asm volatile("red.global.add.v4.f32 [%0], {%1,%2,%3,%4};"
                 :: "l"(p), "f"(a), "f"(b), "f"(c), "f"(d) : "memory");
}
__device__ __forceinline__ void mma_16n8k16(float* c, const uint32_t* a,
                                            uint32_t b0, uint32_t b1) {
    asm volatile(
        "mma.sync.aligned.m16n8k16.row.col.f32.f16.f16.f32 "
        "{%0,%1,%2,%3}, {%4,%5,%6,%7}, {%8,%9}, {%0,%1,%2,%3};"
        : "+f"(c[0]), "+f"(c[1]), "+f"(c[2]), "+f"(c[3])
        : "r"(a[0]), "r"(a[1]), "r"(a[2]), "r"(a[3]), "r"(b0), "r"(b1));
}

// grid-wide barrier (persistent kernel, grid <= resident capacity).
__device__ __forceinline__ void gridbar(int nb) {
    __syncthreads();
    if (threadIdx.x == 0) {
        unsigned old = *(volatile unsigned*)&g_barflag;
        __threadfence();
        unsigned t = atomicAdd(&g_barcnt, 1);
        if (t == (unsigned)nb - 1) {
            g_barcnt = 0;
            __threadfence();
            atomicAdd(&g_barflag, 1);
        } else {
            while (*(volatile unsigned*)&g_barflag == old) {}
        }
        __threadfence();
    }
    __syncthreads();
}

// ---------------- fused relation counting-sort (one launch) ------------------
__global__ void __launch_bounds__(256, 1)
sort_kernel(const int* __restrict__ etype, int E) {
    __shared__ int sh[256];
    __shared__ int ss[256];
    int b = blockIdx.x, nb = gridDim.x, tid = threadIdx.x;

    if (b == 0) g_counts[tid] = 0;
    gridbar(nb);

    sh[tid] = 0;
    __syncthreads();
    for (int e = b * 256 + tid; e < E; e += nb * 256)
        atomicAdd(&sh[etype[e]], 1);
    __syncthreads();
    if (sh[tid]) atomicAdd(&g_counts[tid], sh[tid]);
    gridbar(nb);

    if (b == 0) {
        int c = g_counts[tid];
        ss[tid] = c;
        __syncthreads();
        #pragma unroll
        for (int off = 1; off < 256; off <<= 1) {
            int v = (tid >= off) ? ss[tid - off] : 0;
            __syncthreads();
            ss[tid] += v;
            __syncthreads();
        }
        g_start[tid] = ss[tid] - c;
        g_cursor[tid] = ss[tid] - c;
    }
    gridbar(nb);

    for (int e = b * 256 + tid; e < E; e += nb * 256) {
        int p = atomicAdd(&g_cursor[etype[e]], 1);
        g_perm[p] = e;
    }
}

// W^T[r][n][k] = sum_b comp[r,b] * V[b][k][n]
__global__ void wbuild_kernel(const float* __restrict__ V,
                              const float* __restrict__ comp) {
    __shared__ float sC[RTILE * NB];
    int r0 = blockIdx.y * RTILE;
    for (int i = threadIdx.x; i < RTILE * NB; i += 128) {
        int rr = i / NB, b = i % NB;
        int r = r0 + rr;
        sC[i] = (r < NREL) ? comp[r * NB + b] : 0.f;
    }
    __syncthreads();
    int j = blockIdx.x * 128 + threadIdx.x;
    float acc[RTILE];
    #pragma unroll
    for (int rr = 0; rr < RTILE; rr++) acc[rr] = 0.f;
    #pragma unroll 4
    for (int b = 0; b < NB; b++) {
        float v = V[(size_t)b * (H * H) + j];
        #pragma unroll
        for (int rr = 0; rr < RTILE; rr++) acc[rr] += sC[rr * NB + b] * v;
    }
    int k = j >> 7, n = j & 127;
    #pragma unroll
    for (int rr = 0; rr < RTILE; rr++) {
        int r = r0 + rr;
        if (r < NREL) g_W[(size_t)r * (H * H) + n * 128 + k] = acc[rr];
    }
}

__global__ void relu_kernel(int n) {
    for (int i = blockIdx.x * blockDim.x + threadIdx.x; i < n;
         i += gridDim.x * blockDim.x)
        g_h1[i] = fmaxf(g_h1[i], 0.f);
}

// -------- dense self-loop GEMM: out = x @ W + bias; optional emb gather -----
__global__ void node_gemm_kernel(const float* __restrict__ xin,
                                 const int* __restrict__ nids,   // NULL: direct
                                 float* __restrict__ xcopy,      // NULL: skip
                                 const float* __restrict__ wmat,
                                 const float* __restrict__ bias,
                                 float* __restrict__ out, int n) {
    float* smem = (float*)dyn_smem;
    float* sW = smem;
    float* sX = smem + H * H;
    {
        const float4* s4 = (const float4*)wmat;
        float4* d4 = (float4*)sW;
        for (int i = threadIdx.x; i < (H * H) / 4; i += 256) d4[i] = s4[i];
    }
    int m0 = blockIdx.x * MT;
    int tsize = min(MT, n - m0);
    int mrow = threadIdx.x >> 2, dg = threadIdx.x & 3;
    if (mrow < tsize) {
        int row = m0 + mrow;
        int srow = nids ? nids[row] : row;
        const float4* xr = (const float4*)&xin[(size_t)srow * H];
        #pragma unroll
        for (int i = 0; i < 8; i++) {
            float4 v = xr[dg * 8 + i];
            *(float4*)&sX[mrow * XPITCH + dg * 32 + 4 * i] = v;
            if (xcopy)
                *(float4*)&xcopy[(size_t)row * H + dg * 32 + 4 * i] = v;
        }
    } else {
        float4 z = make_float4(0.f, 0.f, 0.f, 0.f);
        #pragma unroll
        for (int i = 0; i < 8; i++)
            *(float4*)&sX[mrow * XPITCH + dg * 32 + 4 * i] = z;
    }
    __syncthreads();
    int tn = threadIdx.x & 31, tm = threadIdx.x >> 5;
    float acc[8][4];
    #pragma unroll
    for (int r = 0; r < 8; r++)
        #pragma unroll
        for (int c = 0; c < 4; c++) acc[r][c] = 0.f;
    const float* sxb = &sX[tm * 8 * XPITCH];
    #pragma unroll 4
    for (int k = 0; k < H; k++) {
        float4 b = *(const float4*)&sW[k * H + tn * 4];
        #pragma unroll
        for (int r = 0; r < 8; r++) {
            float a = sxb[r * XPITCH + k];
            acc[r][0] += a * b.x; acc[r][1] += a * b.y;
            acc[r][2] += a * b.z; acc[r][3] += a * b.w;
        }
    }
    float4 bj = *(const float4*)&bias[tn * 4];
    #pragma unroll
    for (int r = 0; r < 8; r++) {
        int row = tm * 8 + r;
        if (row < tsize) {
            float4 o = make_float4(acc[r][0] + bj.x, acc[r][1] + bj.y,
                                   acc[r][2] + bj.z, acc[r][3] + bj.w);
            *(float4*)&out[(size_t)(m0 + row) * H + tn * 4] = o;
        }
    }
}

// ---------------- FP16 mma.sync edge GEMM + fused RED.v4 scatter -------------
// CTA: 256 threads = 8 warps, warp tile 32(M) x 64(N), tile 128 edges x 128.
// m16n8k16 f16 with f32 accum: half the LDS bytes + half the MMA count of tf32.
// Paired-k half2 smem layout: within each 16-k group, half2 pairs stored as
// [q0,q4,q1,q5,q2,q6,q3,q7] so thread tig's LDS.64 at 2*tig yields (k-pair 2tig,
// k-pair 2tig+8) = exactly its fragment's two k-chunks.
// B rows n-permuted so each thread's output quad is contiguous (RED.v4).
// norm applied fp32 in the epilogue.
__global__ void __launch_bounds__(256, 1)
edge_mma_kernel(const float* __restrict__ xin,
                const int* __restrict__ src,
                const int* __restrict__ dst,
                const int* __restrict__ perm,
                const float* __restrict__ norm,
                float* __restrict__ hout) {
    uint32_t* sA = (uint32_t*)dyn_smem;      // [128][BPH] half2, paired-k
    uint32_t* sB = sA + 128 * BPH;           // [128][BPH] half2, paired-k + n-perm
    int*   sDst = (int*)(sB + 128 * BPH);    // [EM]
    float* sNrm = (float*)(sDst + EM);       // [EM]

    int tid = threadIdx.x, lane = tid & 31, wid = tid >> 5;
    int g = lane >> 2, tig = lane & 3;
    int wm = wid >> 1, wn = wid & 1;         // 4 x 2 warp grid
    int m0 = wm * 32, n0 = wn * 64;

    int rel = blockIdx.x >> 1;
    int sp  = blockIdx.x & 1;
    int cnt = g_counts[rel], st = g_start[rel];
    int lo = st + (cnt * sp) / ESPLIT;
    int hi = st + (cnt * (sp + 1)) / ESPLIT;
    if (lo >= hi) return;

    // ---- stage B = W^T[rel]: n-permuted rows, paired-k half2, fp16 ----
    // 128 rows x 8 k-groups (16 k each)
    {
        const float* wt = g_W + (size_t)rel * (H * H);
        for (int u = tid; u < 1024; u += 256) {
            int srow = u >> 3;          // stored (logical) row 0..127
            int kg = u & 7;             // 16-col k-group 0..7
            int half = srow >> 6;
            int rem = srow & 63;
            int ni = rem >> 3, tg = (rem >> 1) & 3, bb = rem & 1;
            int an = half * 64 + (ni >> 1) * 16 + tg * 4 + (ni & 1) * 2 + bb;
            const float4* wr = (const float4*)(wt + (size_t)an * H);
            float4 u0 = wr[kg * 4], u1 = wr[kg * 4 + 1];
            float4 u2 = wr[kg * 4 + 2], u3 = wr[kg * 4 + 3];
            uint32_t q0 = h2pack(u0.x, u0.y), q1 = h2pack(u0.z, u0.w);
            uint32_t q2 = h2pack(u1.x, u1.y), q3 = h2pack(u1.z, u1.w);
            uint32_t q4 = h2pack(u2.x, u2.y), q5 = h2pack(u2.z, u2.w);
            uint32_t q6 = h2pack(u3.x, u3.y), q7 = h2pack(u3.z, u3.w);
            uint32_t* d = &sB[srow * BPH + kg * 8];
            *(uint4*)&d[0] = make_uint4(q0, q4, q1, q5);
            *(uint4*)&d[4] = make_uint4(q2, q6, q3, q7);
        }
    }

    int arow = tid >> 1, ahalf = tid & 1;    // 2 staging threads per edge row
    float4 pf[16];
    float pnrm = 0.f;
    int pdst = 0, pvalid = 0;

    // initial prefetch for first tile
    {
        int t0 = lo;
        if (t0 + arow < hi) {
            int e = perm[t0 + arow];
            if (ahalf == 0) { pnrm = norm[e]; pdst = dst[e]; }
            const float4* xr = (const float4*)(xin + (size_t)src[e] * H);
            #pragma unroll
            for (int i = 0; i < 16; i++) pf[i] = xr[ahalf * 16 + i];
            pvalid = 1;
        } else pvalid = 0;
    }

    for (int t0 = lo; t0 < hi; t0 += EM) {
        int tsize = min(EM, hi - t0);
        __syncthreads();   // prev compute done reading sA (also orders sB once)

        // ---- STS: paired-k half2 from prefetch registers ----
        if (pvalid) {
            #pragma unroll
            for (int j = 0; j < 4; j++) {
                int kg = ahalf * 4 + j;
                float4 u0 = pf[4 * j], u1 = pf[4 * j + 1];
                float4 u2 = pf[4 * j + 2], u3 = pf[4 * j + 3];
                uint32_t q0 = h2pack(u0.x, u0.y), q1 = h2pack(u0.z, u0.w);
                uint32_t q2 = h2pack(u1.x, u1.y), q3 = h2pack(u1.z, u1.w);
                uint32_t q4 = h2pack(u2.x, u2.y), q5 = h2pack(u2.z, u2.w);
                uint32_t q6 = h2pack(u3.x, u3.y), q7 = h2pack(u3.z, u3.w);
                uint32_t* d = &sA[arow * BPH + kg * 8];
                *(uint4*)&d[0] = make_uint4(q0, q4, q1, q5);
                *(uint4*)&d[4] = make_uint4(q2, q6, q3, q7);
            }
        } else {
            uint4 z = make_uint4(0, 0, 0, 0);
            #pragma unroll
            for (int j = 0; j < 4; j++) {
                int kg = ahalf * 4 + j;
                uint32_t* d = &sA[arow * BPH + kg * 8];
                *(uint4*)&d[0] = z;
                *(uint4*)&d[4] = z;
            }
        }
        if (ahalf == 0) { sDst[arow] = pdst; sNrm[arow] = pnrm; }
        __syncthreads();

        // ---- prefetch next tile (overlaps with MMA below) ----
        {
            int tn0 = t0 + EM;
            if (tn0 < hi) {
                if (tn0 + arow < hi) {
                    int e = perm[tn0 + arow];
                    if (ahalf == 0) { pnrm = norm[e]; pdst = dst[e]; }
                    const float4* xr =
                        (const float4*)(xin + (size_t)src[e] * H);
                    #pragma unroll
                    for (int i = 0; i < 16; i++) pf[i] = xr[ahalf * 16 + i];
                    pvalid = 1;
                } else pvalid = 0;
            }
        }

        // ---- compute: 8 ksteps of m16n8k16, LDS.64 fragments ----
        float acc[2][8][4];
        #pragma unroll
        for (int mi = 0; mi < 2; mi++)
            #pragma unroll
            for (int ni = 0; ni < 8; ni++)
                #pragma unroll
                for (int c = 0; c < 4; c++) acc[mi][ni][c] = 0.f;

        #pragma unroll
        for (int ks = 0; ks < 8; ks++) {
            int base = ks * 8 + 2 * tig;
            uint32_t a[2][4];
            #pragma unroll
            for (int mi = 0; mi < 2; mi++) {
                uint2 alo = *(const uint2*)&sA[(m0 + mi * 16 + g) * BPH + base];
                uint2 ahi = *(const uint2*)&sA[(m0 + mi * 16 + g + 8) * BPH + base];
                a[mi][0] = alo.x; a[mi][2] = alo.y;
                a[mi][1] = ahi.x; a[mi][3] = ahi.y;
            }
            #pragma unroll
            for (int ni = 0; ni < 8; ni++) {
                uint2 bb = *(const uint2*)&sB[(n0 + ni * 8 + g) * BPH + base];
                mma_16n8k16(acc[0][ni], a[0], bb.x, bb.y);
                mma_16n8k16(acc[1][ni], a[1], bb.x, bb.y);
            }
        }

        // ---- epilogue: scale by norm (fp32) and RED.v4 scatter ----
        #pragma unroll
        for (int mi = 0; mi < 2; mi++) {
            int r0 = m0 + mi * 16 + g;
            int r1 = r0 + 8;
            bool v0 = r0 < tsize, v1 = r1 < tsize;
            float nr0 = sNrm[r0], nr1 = sNrm[r1];
            float* p0 = hout + (size_t)sDst[r0] * H;
            float* p1 = hout + (size_t)sDst[r1] * H;
            #pragma unroll
            for (int q = 0; q < 4; q++) {
                int c = n0 + q * 16 + tig * 4;
                if (v0) red_add_v4(p0 + c,
                                   acc[mi][2 * q][0] * nr0,
                                   acc[mi][2 * q][1] * nr0,
                                   acc[mi][2 * q + 1][0] * nr0,
                                   acc[mi][2 * q + 1][1] * nr0);
                if (v1) red_add_v4(p1 + c,
                                   acc[mi][2 * q][2] * nr1,
                                   acc[mi][2 * q][3] * nr1,
                                   acc[mi][2 * q + 1][2] * nr1,
                                   acc[mi][2 * q + 1][3] * nr1);
            }
        }
    }
}

// ---------------- host orchestration ----------------------------------------
extern "C" void kernel_launch(void* const* d_in, const int* in_sizes, int n_in,
                              void* d_out, int out_size) {
    const int*   nids  = (const int*)d_in[0];
    const int*   src   = (const int*)d_in[1];
    const int*   dst   = (const int*)d_in[2];
    const int*   etype = (const int*)d_in[3];
    const float* norm  = (const float*)d_in[4];
    const float* emb   = (const float*)d_in[6];
    const float* V1    = (const float*)d_in[7];
    const float* comp1 = (const float*)d_in[8];
    const float* loop1 = (const float*)d_in[9];
    const float* bias1 = (const float*)d_in[10];
    const float* V2    = (const float*)d_in[11];
    const float* comp2 = (const float*)d_in[12];
    const float* loop2 = (const float*)d_in[13];
    const float* bias2 = (const float*)d_in[14];
    float* out = (float*)d_out;

    int nN = in_sizes[0];
    int E  = in_sizes[1];

    cudaFuncSetAttribute(node_gemm_kernel,
                         cudaFuncAttributeMaxDynamicSharedMemorySize, SMEM_NODE);
    cudaFuncSetAttribute(edge_mma_kernel,
                         cudaFuncAttributeMaxDynamicSharedMemorySize, SMEM_EDGE);

    float *px0 = nullptr, *ph1 = nullptr;
    int* pperm = nullptr;
    cudaGetSymbolAddress((void**)&px0, g_x0);
    cudaGetSymbolAddress((void**)&ph1, g_h1);
    cudaGetSymbolAddress((void**)&pperm, g_perm);

    dim3 wgrid(H * H / 128, (NREL + RTILE - 1) / RTILE);
    int ngrid = (nN + MT - 1) / MT;
    int egrid = NREL * ESPLIT;

    // launch order chosen so edge_mma_kernel is my 4th launch (ncu window)
    sort_kernel<<<SORTB, 256>>>(etype, E);                               // 0
    wbuild_kernel<<<wgrid, 128>>>(V1, comp1);                            // 1
    node_gemm_kernel<<<ngrid, 256, SMEM_NODE>>>(emb, nids, px0,
                                                loop1, bias1, ph1, nN);  // 2
    edge_mma_kernel<<<egrid, 256, SMEM_EDGE>>>(px0, src, dst, pperm,
                                               norm, ph1);               // 3
    relu_kernel<<<256, 256>>>(nN * H);                                   // 4
    wbuild_kernel<<<wgrid, 128>>>(V2, comp2);                            // 5
    node_gemm_kernel<<<ngrid, 256, SMEM_NODE>>>(ph1, nullptr, nullptr,
                                                loop2, bias2, out, nN);  // 6
    edge_mma_kernel<<<egrid, 256, SMEM_EDGE>>>(ph1, src, dst, pperm,
                                               norm, out);               // 7
}

// round 10
// speedup vs baseline: 2.1096x; 1.3492x over previous
#include <cuda_runtime.h>
#include <cuda_fp16.h>
#include <cstdint>

#define H      128
#define NREL   237
#define NB     100
#define RTILE  16
#define MT     64
#define XPITCH 132
#define MAXN   15000
#define MAXE   400000
#define EM     128        // edges per tile
#define ESPLIT 2          // splits per relation for edge kernel
#define BPH    72         // smem pitch in uint32 (half2); 72%32==8 -> conflict-free LDS.64
#define SORTB  148        // persistent blocks for fused sort

// ---------------- device-global scratch (no runtime allocation) -------------
__device__ uint32_t g_Wh[NREL * 8192];   // per-rel W^T fp16, n-perm + paired-k (7.8MB)
__device__ uint32_t g_xh[MAXN * 64];     // x fp16, paired-k per row (3.8MB)
__device__ float g_h1[MAXN * H];
__device__ int   g_perm[MAXE];
__device__ int   g_counts[256];
__device__ int   g_start[256];
__device__ int   g_cursor[256];
__device__ unsigned g_barcnt;
__device__ unsigned g_barflag;

static const int SMEM_NODE = (H * H + MT * XPITCH) * 4 + MT * 4;     // 99584
static const int SMEM_EDGE = 3 * 128 * BPH * 4 + 2 * 128 * 8;        // 112640

extern __shared__ char dyn_smem[];

// ---------------- PTX helpers ------------------------------------------------
__device__ __forceinline__ uint32_t h2pack(float a, float b) {
    __half2 h = __floats2half2_rn(a, b);   // a -> low, b -> high
    return *(uint32_t*)&h;
}
__device__ __forceinline__ void red_add_v4(float* p, float a, float b,
                                           float c, float d) {
    asm volatile("red.global.add.v4.f32 [%0], {%1,%2,%3,%4};"
                 :: "l"(p), "f"(a), "f"(b), "f"(c), "f"(d) : "memory");
}
__device__ __forceinline__ void mma_16n8k16(float* c, const uint32_t* a,
                                            uint32_t b0, uint32_t b1) {
    asm volatile(
        "mma.sync.aligned.m16n8k16.row.col.f32.f16.f16.f32 "
        "{%0,%1,%2,%3}, {%4,%5,%6,%7}, {%8,%9}, {%0,%1,%2,%3};"
        : "+f"(c[0]), "+f"(c[1]), "+f"(c[2]), "+f"(c[3])
        : "r"(a[0]), "r"(a[1]), "r"(a[2]), "r"(a[3]), "r"(b0), "r"(b1));
}
__device__ __forceinline__ void cpa16(void* s, const void* g) {
    uint32_t sa = (uint32_t)__cvta_generic_to_shared(s);
    asm volatile("cp.async.cg.shared.global [%0], [%1], 16;"
                 :: "r"(sa), "l"(g) : "memory");
}
__device__ __forceinline__ void cpa16z(void* s, const void* g) {
    uint32_t sa = (uint32_t)__cvta_generic_to_shared(s);
    asm volatile("cp.async.cg.shared.global [%0], [%1], 16, 0;"
                 :: "r"(sa), "l"(g) : "memory");
}
#define CPA_COMMIT() asm volatile("cp.async.commit_group;" ::: "memory")
#define CPA_WAIT1()  asm volatile("cp.async.wait_group 1;" ::: "memory")

// pack 16 consecutive floats (4 float4) into paired-k half2 order
// [q0,q4,q1,q5],[q2,q6,q3,q7] and return as two uint4
__device__ __forceinline__ void pack_kgroup(const float4* u, uint4* o0, uint4* o1) {
    uint32_t q0 = h2pack(u[0].x, u[0].y), q1 = h2pack(u[0].z, u[0].w);
    uint32_t q2 = h2pack(u[1].x, u[1].y), q3 = h2pack(u[1].z, u[1].w);
    uint32_t q4 = h2pack(u[2].x, u[2].y), q5 = h2pack(u[2].z, u[2].w);
    uint32_t q6 = h2pack(u[3].x, u[3].y), q7 = h2pack(u[3].z, u[3].w);
    *o0 = make_uint4(q0, q4, q1, q5);
    *o1 = make_uint4(q2, q6, q3, q7);
}

// grid-wide barrier (persistent kernel, grid <= resident capacity).
__device__ __forceinline__ void gridbar(int nb) {
    __syncthreads();
    if (threadIdx.x == 0) {
        unsigned old = *(volatile unsigned*)&g_barflag;
        __threadfence();
        unsigned t = atomicAdd(&g_barcnt, 1);
        if (t == (unsigned)nb - 1) {
            g_barcnt = 0;
            __threadfence();
            atomicAdd(&g_barflag, 1);
        } else {
            while (*(volatile unsigned*)&g_barflag == old) {}
        }
        __threadfence();
    }
    __syncthreads();
}

// ---------------- fused relation counting-sort (one launch) ------------------
__global__ void __launch_bounds__(256, 1)
sort_kernel(const int* __restrict__ etype, int E) {
    __shared__ int sh[256];
    __shared__ int ss[256];
    int b = blockIdx.x, nb = gridDim.x, tid = threadIdx.x;

    if (b == 0) g_counts[tid] = 0;
    gridbar(nb);

    sh[tid] = 0;
    __syncthreads();
    for (int e = b * 256 + tid; e < E; e += nb * 256)
        atomicAdd(&sh[etype[e]], 1);
    __syncthreads();
    if (sh[tid]) atomicAdd(&g_counts[tid], sh[tid]);
    gridbar(nb);

    if (b == 0) {
        int c = g_counts[tid];
        ss[tid] = c;
        __syncthreads();
        #pragma unroll
        for (int off = 1; off < 256; off <<= 1) {
            int v = (tid >= off) ? ss[tid - off] : 0;
            __syncthreads();
            ss[tid] += v;
            __syncthreads();
        }
        g_start[tid] = ss[tid] - c;
        g_cursor[tid] = ss[tid] - c;
    }
    gridbar(nb);

    for (int e = b * 256 + tid; e < E; e += nb * 256) {
        int p = atomicAdd(&g_cursor[etype[e]], 1);
        g_perm[p] = e;
    }
}

// ---- xh gather: g_xh[node] = fp16(emb[nids[node]]) in paired-k layout ------
__global__ void xh_gather_kernel(const float* __restrict__ emb,
                                 const int* __restrict__ nids, int n) {
    int idx = blockIdx.x * blockDim.x + threadIdx.x;
    if (idx >= n * 8) return;
    int node = idx >> 3, kg = idx & 7;
    const float4* xr = (const float4*)emb + (size_t)nids[node] * 32 + kg * 4;
    float4 u[4] = {xr[0], xr[1], xr[2], xr[3]};
    uint4 o0, o1;
    pack_kgroup(u, &o0, &o1);
    uint4* d = (uint4*)(g_xh + (size_t)node * 64 + kg * 8);
    d[0] = o0; d[1] = o1;
}

// ---- relu h1 in place + g_xh = fp16(relu(h1)) paired-k ---------------------
__global__ void relu_xh_kernel(int n) {
    int idx = blockIdx.x * blockDim.x + threadIdx.x;
    if (idx >= n * 8) return;
    int node = idx >> 3, kg = idx & 7;
    float4* hr = (float4*)g_h1 + (size_t)node * 32 + kg * 4;
    float4 u[4];
    #pragma unroll
    for (int i = 0; i < 4; i++) {
        float4 v = hr[i];
        v.x = fmaxf(v.x, 0.f); v.y = fmaxf(v.y, 0.f);
        v.z = fmaxf(v.z, 0.f); v.w = fmaxf(v.w, 0.f);
        hr[i] = v;
        u[i] = v;
    }
    uint4 o0, o1;
    pack_kgroup(u, &o0, &o1);
    uint4* d = (uint4*)(g_xh + (size_t)node * 64 + kg * 8);
    d[0] = o0; d[1] = o1;
}

// ---- wbuildh: g_Wh[r] = fp16(sum_b comp[r,b] V[b])^T, n-perm + paired-k ----
// grid (64, ceil(NREL/RTILE)), block 128. blockIdx.x = k-pair kp, tid = n.
__global__ void wbuildh_kernel(const float* __restrict__ V,
                               const float* __restrict__ comp) {
    __shared__ float sC[RTILE * NB];
    int r0 = blockIdx.y * RTILE;
    for (int i = threadIdx.x; i < RTILE * NB; i += 128) {
        int rr = i / NB, b = i % NB;
        int r = r0 + rr;
        sC[i] = (r < NREL) ? comp[r * NB + b] : 0.f;
    }
    __syncthreads();
    int kp = blockIdx.x;          // k-pair 0..63 (k = 2kp, 2kp+1)
    int n = threadIdx.x;          // 0..127
    float a0[RTILE], a1[RTILE];
    #pragma unroll
    for (int rr = 0; rr < RTILE; rr++) { a0[rr] = 0.f; a1[rr] = 0.f; }
    const float* v0p = V + (size_t)(2 * kp) * 128 + n;
    #pragma unroll 2
    for (int b = 0; b < NB; b++) {
        float v0 = v0p[(size_t)b * (H * H)];
        float v1 = v0p[(size_t)b * (H * H) + 128];
        #pragma unroll
        for (int rr = 0; rr < RTILE; rr++) {
            float c = sC[rr * NB + b];
            a0[rr] += c * v0;
            a1[rr] += c * v1;
        }
    }
    // inverse n-permutation: n -> stored row
    int half = n >> 6, rem = n & 63;
    int qq = rem >> 4, t4 = (rem >> 2) & 3, p = (rem >> 1) & 1, bb = rem & 1;
    int srow = half * 64 + (2 * qq + p) * 8 + t4 * 2 + bb;
    // paired-k position within the 8-uint32 k-group
    int kg = kp >> 3, j0 = kp & 7;
    int pos = (j0 < 4) ? 2 * j0 : 2 * j0 - 7;
    int off = srow * 64 + kg * 8 + pos;
    #pragma unroll
    for (int rr = 0; rr < RTILE; rr++) {
        int r = r0 + rr;
        if (r < NREL) g_Wh[(size_t)r * 8192 + off] = h2pack(a0[rr], a1[rr]);
    }
}

// -------- dense self-loop GEMM: out = x @ W + bias; optional nids gather ----
__global__ void node_gemm_kernel(const float* __restrict__ xin,
                                 const int* __restrict__ nids,   // NULL: direct
                                 const float* __restrict__ wmat,
                                 const float* __restrict__ bias,
                                 float* __restrict__ out, int n) {
    float* smem = (float*)dyn_smem;
    float* sW = smem;
    float* sX = smem + H * H;
    {
        const float4* s4 = (const float4*)wmat;
        float4* d4 = (float4*)sW;
        for (int i = threadIdx.x; i < (H * H) / 4; i += 256) d4[i] = s4[i];
    }
    int m0 = blockIdx.x * MT;
    int tsize = min(MT, n - m0);
    int mrow = threadIdx.x >> 2, dg = threadIdx.x & 3;
    if (mrow < tsize) {
        int row = m0 + mrow;
        int srow = nids ? nids[row] : row;
        const float4* xr = (const float4*)&xin[(size_t)srow * H];
        #pragma unroll
        for (int i = 0; i < 8; i++)
            *(float4*)&sX[mrow * XPITCH + dg * 32 + 4 * i] = xr[dg * 8 + i];
    } else {
        float4 z = make_float4(0.f, 0.f, 0.f, 0.f);
        #pragma unroll
        for (int i = 0; i < 8; i++)
            *(float4*)&sX[mrow * XPITCH + dg * 32 + 4 * i] = z;
    }
    __syncthreads();
    int tn = threadIdx.x & 31, tm = threadIdx.x >> 5;
    float acc[8][4];
    #pragma unroll
    for (int r = 0; r < 8; r++)
        #pragma unroll
        for (int c = 0; c < 4; c++) acc[r][c] = 0.f;
    const float* sxb = &sX[tm * 8 * XPITCH];
    #pragma unroll 4
    for (int k = 0; k < H; k++) {
        float4 b = *(const float4*)&sW[k * H + tn * 4];
        #pragma unroll
        for (int r = 0; r < 8; r++) {
            float a = sxb[r * XPITCH + k];
            acc[r][0] += a * b.x; acc[r][1] += a * b.y;
            acc[r][2] += a * b.z; acc[r][3] += a * b.w;
        }
    }
    float4 bj = *(const float4*)&bias[tn * 4];
    #pragma unroll
    for (int r = 0; r < 8; r++) {
        int row = tm * 8 + r;
        if (row < tsize) {
            float4 o = make_float4(acc[r][0] + bj.x, acc[r][1] + bj.y,
                                   acc[r][2] + bj.z, acc[r][3] + bj.w);
            *(float4*)&out[(size_t)(m0 + row) * H + tn * 4] = o;
        }
    }
}

// ---------------- FP16 mma.sync edge GEMM, cp.async double-buffered ----------
// CTA: 256 threads = 8 warps, warp tile 32(M) x 64(N), tile 128 edges x 128.
// A and B arrive pre-converted/pre-permuted fp16 via cp.async (LDGSTS).
__global__ void __launch_bounds__(256, 1)
edge_mma_kernel(const int* __restrict__ src,
                const int* __restrict__ dst,
                const float* __restrict__ norm,
                float* __restrict__ hout) {
    uint32_t* sB  = (uint32_t*)dyn_smem;          // [128][BPH]
    uint32_t* sA0 = sB + 128 * BPH;               // [128][BPH] buf 0
    uint32_t* sA1 = sA0 + 128 * BPH;              // [128][BPH] buf 1
    int*   sDst = (int*)(sA1 + 128 * BPH);        // [2][128]
    float* sNrm = (float*)(sDst + 256);           // [2][128]

    int tid = threadIdx.x, lane = tid & 31, wid = tid >> 5;
    int g = lane >> 2, tig = lane & 3;
    int wm = wid >> 1, wn = wid & 1;              // 4 x 2 warp grid
    int m0 = wm * 32, n0 = wn * 64;

    int rel = blockIdx.x >> 1;
    int sp  = blockIdx.x & 1;
    int cnt = g_counts[rel], st = g_start[rel];
    int lo = st + (cnt * sp) / ESPLIT;
    int hi = st + (cnt * (sp + 1)) / ESPLIT;
    if (lo >= hi) return;

    // ---- B: straight cp.async copy of pre-permuted fp16 W tile (32KB) ----
    {
        const uint32_t* wb = g_Wh + (size_t)rel * 8192;
        #pragma unroll
        for (int i = 0; i < 8; i++) {
            int c = tid + i * 256;
            int row = c >> 4, cc = c & 15;
            cpa16(&sB[row * BPH + cc * 4], &wb[row * 64 + cc * 4]);
        }
    }

    int arow = tid >> 1, ahalf = tid & 1;

    // issue A tile starting at edge index t0 into buffer bsel
    auto issueA = [&](int t0, uint32_t* sAb, int bsel) {
        int r = t0 + arow;
        uint32_t* sp = sAb + arow * BPH + ahalf * 32;
        if (r < hi) {
            int e = g_perm[r];
            if (ahalf == 0) {
                sDst[bsel * 128 + arow] = dst[e];
                sNrm[bsel * 128 + arow] = norm[e];
            }
            const uint32_t* gp = g_xh + (size_t)src[e] * 64 + ahalf * 32;
            #pragma unroll
            for (int c = 0; c < 8; c++) cpa16(sp + c * 4, gp + c * 4);
        } else {
            #pragma unroll
            for (int c = 0; c < 8; c++) cpa16z(sp + c * 4, g_xh);
        }
    };

    int ntiles = (hi - lo + EM - 1) / EM;
    issueA(lo, sA0, 0);
    CPA_COMMIT();                                  // group0 = B + A(0)

    for (int it = 0; it < ntiles; it++) {
        int t0 = lo + it * EM;
        if (it + 1 < ntiles)
            issueA(t0 + EM, ((it + 1) & 1) ? sA1 : sA0, (it + 1) & 1);
        CPA_COMMIT();
        CPA_WAIT1();                               // tile it's data resident
        __syncthreads();

        uint32_t* sA = (it & 1) ? sA1 : sA0;
        int bsel = it & 1;
        int tsize = min(EM, hi - t0);

        float acc[2][8][4];
        #pragma unroll
        for (int mi = 0; mi < 2; mi++)
            #pragma unroll
            for (int ni = 0; ni < 8; ni++)
                #pragma unroll
                for (int c = 0; c < 4; c++) acc[mi][ni][c] = 0.f;

        #pragma unroll
        for (int ks = 0; ks < 8; ks++) {
            int base = ks * 8 + 2 * tig;
            uint32_t a[2][4];
            #pragma unroll
            for (int mi = 0; mi < 2; mi++) {
                uint2 alo = *(const uint2*)&sA[(m0 + mi * 16 + g) * BPH + base];
                uint2 ahi = *(const uint2*)&sA[(m0 + mi * 16 + g + 8) * BPH + base];
                a[mi][0] = alo.x; a[mi][2] = alo.y;
                a[mi][1] = ahi.x; a[mi][3] = ahi.y;
            }
            #pragma unroll
            for (int ni = 0; ni < 8; ni++) {
                uint2 bb = *(const uint2*)&sB[(n0 + ni * 8 + g) * BPH + base];
                mma_16n8k16(acc[0][ni], a[0], bb.x, bb.y);
                mma_16n8k16(acc[1][ni], a[1], bb.x, bb.y);
            }
        }

        // ---- epilogue: scale by norm (fp32) and RED.v4 scatter ----
        #pragma unroll
        for (int mi = 0; mi < 2; mi++) {
            int r0 = m0 + mi * 16 + g;
            int r1 = r0 + 8;
            bool v0 = r0 < tsize, v1 = r1 < tsize;
            float nr0 = sNrm[bsel * 128 + r0], nr1 = sNrm[bsel * 128 + r1];
            float* p0 = hout + (size_t)sDst[bsel * 128 + r0] * H;
            float* p1 = hout + (size_t)sDst[bsel * 128 + r1] * H;
            #pragma unroll
            for (int q = 0; q < 4; q++) {
                int c = n0 + q * 16 + tig * 4;
                if (v0) red_add_v4(p0 + c,
                                   acc[mi][2 * q][0] * nr0,
                                   acc[mi][2 * q][1] * nr0,
                                   acc[mi][2 * q + 1][0] * nr0,
                                   acc[mi][2 * q + 1][1] * nr0);
                if (v1) red_add_v4(p1 + c,
                                   acc[mi][2 * q][2] * nr1,
                                   acc[mi][2 * q][3] * nr1,
                                   acc[mi][2 * q + 1][2] * nr1,
                                   acc[mi][2 * q + 1][3] * nr1);
            }
        }
        __syncthreads();   // all reads of sA[bsel] done before it's refilled
    }
}

// ---------------- host orchestration ----------------------------------------
extern "C" void kernel_launch(void* const* d_in, const int* in_sizes, int n_in,
                              void* d_out, int out_size) {
    const int*   nids  = (const int*)d_in[0];
    const int*   src   = (const int*)d_in[1];
    const int*   dst   = (const int*)d_in[2];
    const int*   etype = (const int*)d_in[3];
    const float* norm  = (const float*)d_in[4];
    const float* emb   = (const float*)d_in[6];
    const float* V1    = (const float*)d_in[7];
    const float* comp1 = (const float*)d_in[8];
    const float* loop1 = (const float*)d_in[9];
    const float* bias1 = (const float*)d_in[10];
    const float* V2    = (const float*)d_in[11];
    const float* comp2 = (const float*)d_in[12];
    const float* loop2 = (const float*)d_in[13];
    const float* bias2 = (const float*)d_in[14];
    float* out = (float*)d_out;

    int nN = in_sizes[0];
    int E  = in_sizes[1];

    cudaFuncSetAttribute(node_gemm_kernel,
                         cudaFuncAttributeMaxDynamicSharedMemorySize, SMEM_NODE);
    cudaFuncSetAttribute(edge_mma_kernel,
                         cudaFuncAttributeMaxDynamicSharedMemorySize, SMEM_EDGE);

    float* ph1 = nullptr;
    cudaGetSymbolAddress((void**)&ph1, g_h1);

    dim3 wgrid(64, (NREL + RTILE - 1) / RTILE);
    int ngrid = (nN + MT - 1) / MT;
    int egrid = NREL * ESPLIT;
    int xgrid = (nN * 8 + 255) / 256;

    sort_kernel<<<SORTB, 256>>>(etype, E);                               // 0
    xh_gather_kernel<<<xgrid, 256>>>(emb, nids, nN);                     // 1
    wbuildh_kernel<<<wgrid, 128>>>(V1, comp1);                           // 2
    node_gemm_kernel<<<ngrid, 256, SMEM_NODE>>>(emb, nids,
                                                loop1, bias1, ph1, nN);  // 3
    edge_mma_kernel<<<egrid, 256, SMEM_EDGE>>>(src, dst, norm, ph1);     // 4
    relu_xh_kernel<<<xgrid, 256>>>(nN);                                  // 5
    wbuildh_kernel<<<wgrid, 128>>>(V2, comp2);                           // 6
    node_gemm_kernel<<<ngrid, 256, SMEM_NODE>>>(ph1, nullptr,
                                                loop2, bias2, out, nN);  // 7
    edge_mma_kernel<<<egrid, 256, SMEM_EDGE>>>(src, dst, norm, out);     // 8
}